// round 5
// baseline (speedup 1.0000x reference)
#include <cuda_runtime.h>
#include <cuda_bf16.h>
#include <math.h>

#define N_NODES 8192
#define EMBED   64
#define HID0    256
#define HID1    256
#define HID2    128
#define ACTION  8192
#define IN_SIZE (N_NODES + EMBED)   // 8256
#define ROW_F4  (IN_SIZE / 4)       // 2064
#define RPB 8

#define NT_BLOCKS   64               // k_t blocks in mega kernel
#define TAIL_BLOCK  64               // tail block index
#define FC4_FIRST   65               // fc4 blocks: 65..320 (256 blocks, 32 outputs each)
#define MEGA_BLOCKS (65 + ACTION / 32)

// ---- scratch ----
__device__ float g_x[N_NODES];
__device__ float g_s[N_NODES];
__device__ float g_t[HID0];
__device__ float g_fc1p[HID0];
__device__ float g_y3[HID2];
__device__ unsigned int g_ctr_t;
__device__ unsigned int g_flag_y3;
__device__ float g_dummy;

// K1: extract diagonal + reset flags
__global__ void k_diag(const float* __restrict__ state) {
    if (blockIdx.x == 0 && threadIdx.x == 0) { g_ctr_t = 0u; g_flag_y3 = 0u; }
    int i = blockIdx.x * blockDim.x + threadIdx.x;
    if (i < N_NODES) g_x[i] = state[(size_t)i * (N_NODES + 1)];
}

// K2: blocks [0,1024): s = state@x - x^2 ; blocks [1024,1280): fc1 partials
__global__ void __launch_bounds__(256) k_matvec_fc1p(const float* __restrict__ state,
                                                     const int* __restrict__ start_p,
                                                     const float* __restrict__ fc1_w) {
    if (blockIdx.x < N_NODES / RPB) {
        int r0 = blockIdx.x * RPB;
        const float4* __restrict__ base = (const float4*)(state + (size_t)r0 * N_NODES);
        const float4* __restrict__ xp = (const float4*)g_x;
        float acc[RPB];
        #pragma unroll
        for (int r = 0; r < RPB; r++) acc[r] = 0.0f;
        for (int j = threadIdx.x; j < N_NODES / 4; j += 256) {
            float4 xv = xp[j];
            #pragma unroll
            for (int r = 0; r < RPB; r++) {
                float4 a = base[(size_t)r * (N_NODES / 4) + j];
                acc[r] += a.x * xv.x + a.y * xv.y + a.z * xv.z + a.w * xv.w;
            }
        }
        int lane = threadIdx.x & 31, wid = threadIdx.x >> 5;
        #pragma unroll
        for (int r = 0; r < RPB; r++)
            #pragma unroll
            for (int o = 16; o; o >>= 1) acc[r] += __shfl_down_sync(0xffffffffu, acc[r], o);
        __shared__ float sh[RPB][8];
        if (lane == 0) {
            #pragma unroll
            for (int r = 0; r < RPB; r++) sh[r][wid] = acc[r];
        }
        __syncthreads();
        if (threadIdx.x < RPB * 8) {
            int r = threadIdx.x >> 3, w = threadIdx.x & 7;
            float v = sh[r][w];
            v += __shfl_down_sync(0xffffffffu, v, 4, 8);
            v += __shfl_down_sync(0xffffffffu, v, 2, 8);
            v += __shfl_down_sync(0xffffffffu, v, 1, 8);
            if (w == 0) {
                int row = r0 + r;
                float xi = g_x[row];
                g_s[row] = v - xi * xi;
            }
        }
    } else {
        int r = blockIdx.x - N_NODES / RPB;
        int st = *start_p;
        const float4* __restrict__ w4 = (const float4*)(fc1_w + (size_t)r * IN_SIZE);
        const float4* __restrict__ s4 = (const float4*)(state + (size_t)st * N_NODES);
        float acc = 0.0f;
        #pragma unroll 8
        for (int j = threadIdx.x; j < N_NODES / 4; j += 256) {
            float4 a = w4[j];
            float4 b = s4[j];
            acc += a.x * b.x + a.y * b.y + a.z * b.z + a.w * b.w;
        }
        int lane = threadIdx.x & 31, wid = threadIdx.x >> 5;
        #pragma unroll
        for (int o = 16; o; o >>= 1) acc += __shfl_down_sync(0xffffffffu, acc, o);
        __shared__ float sh2[8];
        if (lane == 0) sh2[wid] = acc;
        __syncthreads();
        if (threadIdx.x < 8) {
            float v = sh2[threadIdx.x];
            v += __shfl_down_sync(0xffu, v, 4, 8);
            v += __shfl_down_sync(0xffu, v, 2, 8);
            v += __shfl_down_sync(0xffu, v, 1, 8);
            if (threadIdx.x == 0) g_fc1p[r] = v;
        }
    }
}

// K3 MEGA: blocks 0..63 k_t -> counter; block 64 tail (spins on counter);
//          blocks 65.. fc4 (warm L2 + preload weights, spin on y3 flag).
__global__ void __launch_bounds__(256, 3) k_mega(const float* __restrict__ state,
                                                 const int* __restrict__ start_p,
                                                 const float* __restrict__ gc1_w,
                                                 const float* __restrict__ gc1_b,
                                                 const float* __restrict__ gc2_w,
                                                 const float* __restrict__ gc2_b,
                                                 const float* __restrict__ fc1_w,
                                                 const float* __restrict__ fc1_b,
                                                 const float* __restrict__ fc2_w,
                                                 const float* __restrict__ fc2_b,
                                                 const float* __restrict__ fc3_w,
                                                 const float* __restrict__ fc3_b,
                                                 const float* __restrict__ fc4_w,
                                                 const float* __restrict__ fc4_b,
                                                 float* __restrict__ out) {
    int tid = threadIdx.x;
    int lane = tid & 31, warp = tid >> 5;

    if (blockIdx.x < NT_BLOCKS) {
        // ---- k_t: t[j0..j0+3] ----
        int j0 = blockIdx.x * 4;
        int st = *start_p;
        float w0 = gc1_w[j0], w1 = gc1_w[j0 + 1], w2 = gc1_w[j0 + 2], w3 = gc1_w[j0 + 3];
        float b0 = gc1_b[j0], b1 = gc1_b[j0 + 1], b2 = gc1_b[j0 + 2], b3 = gc1_b[j0 + 3];
        const float* __restrict__ row = state + (size_t)st * N_NODES;
        float a0 = 0.f, a1 = 0.f, a2 = 0.f, a3 = 0.f;
        for (int i = tid; i < N_NODES; i += 256) {
            float a = (i == st) ? 0.0f : row[i];
            float s = g_s[i];
            a0 += a * fmaxf(fmaf(s, w0, b0), 0.0f);
            a1 += a * fmaxf(fmaf(s, w1, b1), 0.0f);
            a2 += a * fmaxf(fmaf(s, w2, b2), 0.0f);
            a3 += a * fmaxf(fmaf(s, w3, b3), 0.0f);
        }
        float acc[4] = {a0, a1, a2, a3};
        #pragma unroll
        for (int r = 0; r < 4; r++)
            #pragma unroll
            for (int o = 16; o; o >>= 1) acc[r] += __shfl_down_sync(0xffffffffu, acc[r], o);
        __shared__ float sh[4][8];
        if (lane == 0) {
            #pragma unroll
            for (int r = 0; r < 4; r++) sh[r][warp] = acc[r];
        }
        __syncthreads();
        if (tid < 32) {
            int r = tid >> 3, w = tid & 7;
            float v = sh[r][w];
            v += __shfl_down_sync(0xffffffffu, v, 4, 8);
            v += __shfl_down_sync(0xffffffffu, v, 2, 8);
            v += __shfl_down_sync(0xffffffffu, v, 1, 8);
            if (w == 0) g_t[j0 + r] = v;
        }
        __syncthreads();
        if (tid == 0) { __threadfence(); atomicAdd(&g_ctr_t, 1u); }

    } else if (blockIdx.x == TAIL_BLOCK) {
        // ---- tail: emb -> fc1 finish -> fc2 -> fc3 ----
        __shared__ float ts[HID0];
        __shared__ float part[4][EMBED];
        __shared__ float hv[EMBED];
        __shared__ float emb[EMBED];
        __shared__ float y1s[HID0];
        __shared__ float y2s[HID1];
        __shared__ float red[1];

        if (tid == 0) {
            while (atomicAdd(&g_ctr_t, 0u) < NT_BLOCKS) __nanosleep(64);
            __threadfence();
        }
        __syncthreads();
        if (tid < HID0) ts[tid] = __ldcg(&g_t[tid]);
        __syncthreads();

        // Stage A: u[c] = sum_j ts[j]*gc2_w[j,c]; 4 partials of 64 j's.
        {
            int c = tid & 63, p = tid >> 6;
            float u = 0.0f;
            #pragma unroll 8
            for (int j = p * 64; j < p * 64 + 64; j++)
                u = fmaf(ts[j], gc2_w[j * EMBED + c], u);
            part[p][c] = u;
        }
        __syncthreads();
        if (tid < EMBED) {
            float h = part[0][tid] + part[1][tid] + part[2][tid] + part[3][tid] + gc2_b[tid];
            hv[tid] = fmaxf(h, 0.0f);
        }
        __syncthreads();
        if (tid < 32) {
            float m = fmaxf(hv[tid], hv[tid + 32]);
            #pragma unroll
            for (int o = 16; o; o >>= 1) m = fmaxf(m, __shfl_xor_sync(0xffffffffu, m, o));
            float s = expf(hv[tid] - m) + expf(hv[tid + 32] - m);
            #pragma unroll
            for (int o = 16; o; o >>= 1) s += __shfl_xor_sync(0xffffffffu, s, o);
            if (tid == 0) red[0] = m + logf(s);
        }
        __syncthreads();
        if (tid < EMBED) emb[tid] = hv[tid] - red[0];
        __syncthreads();

        // Stage B: fc1 finish — warp per row, coalesced 256B row reads.
        {
            const float2* __restrict__ e2 = (const float2*)emb;
            float2 ev = e2[lane];
            for (int r = warp * 32; r < warp * 32 + 32; r++) {
                const float2* __restrict__ w2 =
                    (const float2*)(fc1_w + (size_t)r * IN_SIZE + N_NODES);
                float2 w = w2[lane];
                float a = w.x * ev.x + w.y * ev.y;
                #pragma unroll
                for (int o = 16; o; o >>= 1) a += __shfl_down_sync(0xffffffffu, a, o);
                if (lane == 0) y1s[r] = fmaxf(a + g_fc1p[r] + fc1_b[r], 0.0f);
            }
        }
        __syncthreads();

        // Stage C: fc2 — warp per output row (1KB coalesced), 32 rows/warp.
        {
            const float4* __restrict__ y4 = (const float4*)y1s;
            float4 ya = y4[lane], yb = y4[lane + 32];
            for (int o = warp * 32; o < warp * 32 + 32; o++) {
                const float4* __restrict__ w4 = (const float4*)(fc2_w + (size_t)o * HID0);
                float4 wa = w4[lane], wb = w4[lane + 32];
                float a = wa.x * ya.x + wa.y * ya.y + wa.z * ya.z + wa.w * ya.w +
                          wb.x * yb.x + wb.y * yb.y + wb.z * yb.z + wb.w * yb.w;
                #pragma unroll
                for (int off = 16; off; off >>= 1) a += __shfl_down_sync(0xffffffffu, a, off);
                if (lane == 0) y2s[o] = fmaxf(a + fc2_b[o], 0.0f);
            }
        }
        __syncthreads();

        // Stage D: fc3 — warp per output row, 16 rows/warp.
        {
            const float4* __restrict__ y4 = (const float4*)y2s;
            float4 ya = y4[lane], yb = y4[lane + 32];
            for (int o = warp * 16; o < warp * 16 + 16; o++) {
                const float4* __restrict__ w4 = (const float4*)(fc3_w + (size_t)o * HID1);
                float4 wa = w4[lane], wb = w4[lane + 32];
                float a = wa.x * ya.x + wa.y * ya.y + wa.z * ya.z + wa.w * ya.w +
                          wb.x * yb.x + wb.y * yb.y + wb.z * yb.z + wb.w * yb.w;
                #pragma unroll
                for (int off = 16; off; off >>= 1) a += __shfl_down_sync(0xffffffffu, a, off);
                if (lane == 0) g_y3[o] = fmaxf(a + fc3_b[o], 0.0f);
            }
        }
        __syncthreads();
        if (tid == 0) { __threadfence(); atomicExch(&g_flag_y3, 1u); }

    } else {
        // ---- fc4: 32 outputs per block; warm L2 + preload while spinning ----
        int bi = blockIdx.x - FC4_FIRST;          // 0..255
        int a0 = bi * 32 + warp * 4;              // 4 outputs per warp

        // 1) warm tail weights into L2 (gc2_w 4096 f4 | fc2_w 16384 | fc3_w 8192 | fc1tail 4096)
        {
            int idx = bi * 256 + tid;             // 0..65535, need 32768
            float accw = 0.0f;
            if (idx < 4096) {
                float4 v = ((const float4*)gc2_w)[idx];
                accw = v.x + v.y + v.z + v.w;
            } else if (idx < 20480) {
                float4 v = ((const float4*)fc2_w)[idx - 4096];
                accw = v.x + v.y + v.z + v.w;
            } else if (idx < 28672) {
                float4 v = ((const float4*)fc3_w)[idx - 20480];
                accw = v.x + v.y + v.z + v.w;
            } else if (idx < 32768) {
                int t2 = idx - 28672;
                int r = t2 >> 4, c = t2 & 15;
                float4 v = ((const float4*)fc1_w)[(size_t)r * ROW_F4 + (N_NODES / 4) + c];
                accw = v.x + v.y + v.z + v.w;
            }
            if (accw == 1.2345e30f) g_dummy = accw;   // keep loads live
        }

        // 2) preload this warp's fc4 rows + biases into registers
        float4 w0 = ((const float4*)(fc4_w + (size_t)(a0 + 0) * HID2))[lane];
        float4 w1 = ((const float4*)(fc4_w + (size_t)(a0 + 1) * HID2))[lane];
        float4 w2 = ((const float4*)(fc4_w + (size_t)(a0 + 2) * HID2))[lane];
        float4 w3 = ((const float4*)(fc4_w + (size_t)(a0 + 3) * HID2))[lane];
        float b0 = fc4_b[a0], b1 = fc4_b[a0 + 1], b2 = fc4_b[a0 + 2], b3 = fc4_b[a0 + 3];

        // 3) spin for y3
        if (tid == 0) {
            while (atomicAdd(&g_flag_y3, 0u) == 0u) __nanosleep(64);
            __threadfence();
        }
        __syncthreads();

        float4 y = __ldcg((const float4*)g_y3 + lane);
        float d0 = w0.x * y.x + w0.y * y.y + w0.z * y.z + w0.w * y.w;
        float d1 = w1.x * y.x + w1.y * y.y + w1.z * y.z + w1.w * y.w;
        float d2 = w2.x * y.x + w2.y * y.y + w2.z * y.z + w2.w * y.w;
        float d3 = w3.x * y.x + w3.y * y.y + w3.z * y.z + w3.w * y.w;
        #pragma unroll
        for (int o = 16; o; o >>= 1) {
            d0 += __shfl_down_sync(0xffffffffu, d0, o);
            d1 += __shfl_down_sync(0xffffffffu, d1, o);
            d2 += __shfl_down_sync(0xffffffffu, d2, o);
            d3 += __shfl_down_sync(0xffffffffu, d3, o);
        }
        if (lane == 0) {
            out[a0 + 0] = fmaxf(d0 + b0, 0.0f);
            out[a0 + 1] = fmaxf(d1 + b1, 0.0f);
            out[a0 + 2] = fmaxf(d2 + b2, 0.0f);
            out[a0 + 3] = fmaxf(d3 + b3, 0.0f);
        }
    }
}

extern "C" void kernel_launch(void* const* d_in, const int* in_sizes, int n_in,
                              void* d_out, int out_size) {
    const float* state = (const float*)d_in[0];
    const int*   start = (const int*)d_in[1];
    const float* gc1_w = (const float*)d_in[2];
    const float* gc1_b = (const float*)d_in[3];
    const float* gc2_w = (const float*)d_in[4];
    const float* gc2_b = (const float*)d_in[5];
    const float* fc1_w = (const float*)d_in[6];
    const float* fc1_b = (const float*)d_in[7];
    const float* fc2_w = (const float*)d_in[8];
    const float* fc2_b = (const float*)d_in[9];
    const float* fc3_w = (const float*)d_in[10];
    const float* fc3_b = (const float*)d_in[11];
    const float* fc4_w = (const float*)d_in[12];
    const float* fc4_b = (const float*)d_in[13];
    float* out = (float*)d_out;

    k_diag<<<N_NODES / 256, 256>>>(state);
    k_matvec_fc1p<<<N_NODES / RPB + HID0, 256>>>(state, start, fc1_w);
    k_mega<<<MEGA_BLOCKS, 256>>>(state, start, gc1_w, gc1_b, gc2_w, gc2_b,
                                 fc1_w, fc1_b, fc2_w, fc2_b, fc3_w, fc3_b,
                                 fc4_w, fc4_b, out);
}

// round 6
// speedup vs baseline: 1.2145x; 1.2145x over previous
#include <cuda_runtime.h>
#include <cuda_bf16.h>
#include <math.h>

#define N_NODES 8192
#define EMBED   64
#define HID0    256
#define HID1    256
#define HID2    128
#define ACTION  8192
#define IN_SIZE (N_NODES + EMBED)   // 8256
#define ROW_F4  (IN_SIZE / 4)       // 2064
#define RPB 8

#if defined(__CUDA_ARCH__) && (__CUDA_ARCH__ >= 900)
#define PDL_TRIGGER()  cudaTriggerProgrammaticLaunchCompletion()
#define PDL_WAIT()     cudaGridDependencySynchronize()
#else
#define PDL_TRIGGER()
#define PDL_WAIT()
#endif

// ---- scratch ----
__device__ float g_x[N_NODES];
__device__ float g_s[N_NODES];
__device__ float g_t[HID0];
__device__ float g_fc1p[HID0];
__device__ float g_y3[HID2];
__device__ float g_dummy;

// K1: extract diagonal
__global__ void k_diag(const float* __restrict__ state) {
    PDL_TRIGGER();
    int i = blockIdx.x * blockDim.x + threadIdx.x;
    if (i < N_NODES) g_x[i] = state[(size_t)i * (N_NODES + 1)];
}

// K2: blocks [0,1024): s = state@x - x^2 (waits on diag via PDL)
//     blocks [1024,1280): fc1 partials (independent of diag -> overlap it)
__global__ void __launch_bounds__(256) k_matvec_fc1p(const float* __restrict__ state,
                                                     const int* __restrict__ start_p,
                                                     const float* __restrict__ fc1_w) {
    PDL_TRIGGER();
    if (blockIdx.x < N_NODES / RPB) {
        PDL_WAIT();   // need g_x from k_diag
        int r0 = blockIdx.x * RPB;
        const float4* __restrict__ base = (const float4*)(state + (size_t)r0 * N_NODES);
        const float4* __restrict__ xp = (const float4*)g_x;
        float acc[RPB];
        #pragma unroll
        for (int r = 0; r < RPB; r++) acc[r] = 0.0f;
        for (int j = threadIdx.x; j < N_NODES / 4; j += 256) {
            float4 xv = xp[j];
            #pragma unroll
            for (int r = 0; r < RPB; r++) {
                float4 a = base[(size_t)r * (N_NODES / 4) + j];
                acc[r] += a.x * xv.x + a.y * xv.y + a.z * xv.z + a.w * xv.w;
            }
        }
        int lane = threadIdx.x & 31, wid = threadIdx.x >> 5;
        #pragma unroll
        for (int r = 0; r < RPB; r++)
            #pragma unroll
            for (int o = 16; o; o >>= 1) acc[r] += __shfl_down_sync(0xffffffffu, acc[r], o);
        __shared__ float sh[RPB][8];
        if (lane == 0) {
            #pragma unroll
            for (int r = 0; r < RPB; r++) sh[r][wid] = acc[r];
        }
        __syncthreads();
        if (threadIdx.x < RPB * 8) {
            int r = threadIdx.x >> 3, w = threadIdx.x & 7;
            float v = sh[r][w];
            v += __shfl_down_sync(0xffffffffu, v, 4, 8);
            v += __shfl_down_sync(0xffffffffu, v, 2, 8);
            v += __shfl_down_sync(0xffffffffu, v, 1, 8);
            if (w == 0) {
                int row = r0 + r;
                float xi = g_x[row];
                g_s[row] = v - xi * xi;
            }
        }
    } else {
        // fc1 partial: independent of k_diag — runs immediately.
        int r = blockIdx.x - N_NODES / RPB;
        int st = *start_p;
        const float4* __restrict__ w4 = (const float4*)(fc1_w + (size_t)r * IN_SIZE);
        const float4* __restrict__ s4 = (const float4*)(state + (size_t)st * N_NODES);
        float acc = 0.0f;
        #pragma unroll 8
        for (int j = threadIdx.x; j < N_NODES / 4; j += 256) {
            float4 a = w4[j];
            float4 b = s4[j];
            acc += a.x * b.x + a.y * b.y + a.z * b.z + a.w * b.w;
        }
        int lane = threadIdx.x & 31, wid = threadIdx.x >> 5;
        #pragma unroll
        for (int o = 16; o; o >>= 1) acc += __shfl_down_sync(0xffffffffu, acc, o);
        __shared__ float sh2[8];
        if (lane == 0) sh2[wid] = acc;
        __syncthreads();
        if (threadIdx.x < 8) {
            float v = sh2[threadIdx.x];
            v += __shfl_down_sync(0xffu, v, 4, 8);
            v += __shfl_down_sync(0xffu, v, 2, 8);
            v += __shfl_down_sync(0xffu, v, 1, 8);
            if (threadIdx.x == 0) g_fc1p[r] = v;
        }
    }
}

// K3: blocks [0,64): k_t (waits on matvec); blocks [64,128): L2 prefetch (no wait).
__global__ void __launch_bounds__(256) k_t_pf(const float* __restrict__ state,
                                              const int* __restrict__ start_p,
                                              const float* __restrict__ gc1_w,
                                              const float* __restrict__ gc1_b,
                                              const float* __restrict__ gc2_w,
                                              const float* __restrict__ fc1_w,
                                              const float* __restrict__ fc2_w,
                                              const float* __restrict__ fc3_w,
                                              const float* __restrict__ fc4_w) {
    PDL_TRIGGER();
    if (blockIdx.x < 64) {
        int j0 = blockIdx.x * 4;
        float w0 = gc1_w[j0], w1 = gc1_w[j0 + 1], w2 = gc1_w[j0 + 2], w3 = gc1_w[j0 + 3];
        float b0 = gc1_b[j0], b1 = gc1_b[j0 + 1], b2 = gc1_b[j0 + 2], b3 = gc1_b[j0 + 3];
        int st = *start_p;
        const float* __restrict__ row = state + (size_t)st * N_NODES;
        PDL_WAIT();   // need g_s
        float a0 = 0.f, a1 = 0.f, a2 = 0.f, a3 = 0.f;
        for (int i = threadIdx.x; i < N_NODES; i += 256) {
            float a = (i == st) ? 0.0f : row[i];
            float s = g_s[i];
            a0 += a * fmaxf(fmaf(s, w0, b0), 0.0f);
            a1 += a * fmaxf(fmaf(s, w1, b1), 0.0f);
            a2 += a * fmaxf(fmaf(s, w2, b2), 0.0f);
            a3 += a * fmaxf(fmaf(s, w3, b3), 0.0f);
        }
        float acc[4] = {a0, a1, a2, a3};
        int lane = threadIdx.x & 31, wid = threadIdx.x >> 5;
        #pragma unroll
        for (int r = 0; r < 4; r++)
            #pragma unroll
            for (int o = 16; o; o >>= 1) acc[r] += __shfl_down_sync(0xffffffffu, acc[r], o);
        __shared__ float sh[4][8];
        if (lane == 0) {
            #pragma unroll
            for (int r = 0; r < 4; r++) sh[r][wid] = acc[r];
        }
        __syncthreads();
        if (threadIdx.x < 32) {
            int r = threadIdx.x >> 3, w = threadIdx.x & 7;
            float v = sh[r][w];
            v += __shfl_down_sync(0xffffffffu, v, 4, 8);
            v += __shfl_down_sync(0xffffffffu, v, 2, 8);
            v += __shfl_down_sync(0xffffffffu, v, 1, 8);
            if (w == 0) g_t[j0 + r] = v;
        }
    } else {
        // Prefetch downstream weights into L2; overlaps matvec tail + k_t.
        int tid = (blockIdx.x - 64) * 256 + threadIdx.x;
        const int stride = 64 * 256;
        float acc = 0.0f;
        const float4* w;
        w = (const float4*)gc2_w;
        for (int i = tid; i < HID0 * EMBED / 4; i += stride) { float4 v = w[i]; acc += v.x + v.y + v.z + v.w; }
        w = (const float4*)fc2_w;
        for (int i = tid; i < HID1 * HID0 / 4; i += stride) { float4 v = w[i]; acc += v.x + v.y + v.z + v.w; }
        w = (const float4*)fc3_w;
        for (int i = tid; i < HID2 * HID1 / 4; i += stride) { float4 v = w[i]; acc += v.x + v.y + v.z + v.w; }
        w = (const float4*)fc4_w;
        for (int i = tid; i < ACTION * HID2 / 4; i += stride) { float4 v = w[i]; acc += v.x + v.y + v.z + v.w; }
        w = (const float4*)fc1_w;
        for (int i = tid; i < HID0 * 16; i += stride) {
            int r = i >> 4, c = i & 15;
            float4 v = w[(size_t)r * ROW_F4 + (N_NODES / 4) + c];
            acc += v.x + v.y + v.z + v.w;
        }
        if (acc == 1.2345e30f) g_dummy = acc;
    }
}

// K4 (1 block, 1024 threads): emb -> fc1 finish -> fc2 -> fc3.
// Preloads gc2_w into registers BEFORE gridsync (overlaps k_t).
__global__ void __launch_bounds__(1024) k_tail(const float* __restrict__ gc2_w,
                                               const float* __restrict__ gc2_b,
                                               const float* __restrict__ fc1_w,
                                               const float* __restrict__ fc1_b,
                                               const float* __restrict__ fc2_w,
                                               const float* __restrict__ fc2_b,
                                               const float* __restrict__ fc3_w,
                                               const float* __restrict__ fc3_b) {
    PDL_TRIGGER();
    __shared__ float ts[HID0];
    __shared__ float part[16][EMBED];
    __shared__ float hv[EMBED];
    __shared__ float emb[EMBED];
    __shared__ float y1s[HID0];
    __shared__ float y2s[HID1];
    __shared__ float red[1];
    int tid = threadIdx.x;
    int c = tid & 63;
    int p = tid >> 6;          // 0..15

    // Preload gc2_w slice for stage A (independent of k_t) — 16 regs.
    float wreg[16];
    #pragma unroll
    for (int i = 0; i < 16; i++) wreg[i] = gc2_w[(p * 16 + i) * EMBED + c];
    float bias = (tid < EMBED) ? gc2_b[tid] : 0.0f;

    PDL_WAIT();   // need g_t, g_fc1p

    if (tid < HID0) ts[tid] = g_t[tid];
    __syncthreads();

    // Stage A
    {
        float u = 0.0f;
        #pragma unroll
        for (int i = 0; i < 16; i++) u = fmaf(ts[p * 16 + i], wreg[i], u);
        part[p][c] = u;
    }
    __syncthreads();
    if (tid < EMBED) {
        float h = 0.0f;
        #pragma unroll
        for (int q = 0; q < 16; q++) h += part[q][tid];
        hv[tid] = fmaxf(h + bias, 0.0f);
    }
    __syncthreads();
    if (tid < 32) {
        float m = fmaxf(hv[tid], hv[tid + 32]);
        #pragma unroll
        for (int o = 16; o; o >>= 1) m = fmaxf(m, __shfl_xor_sync(0xffffffffu, m, o));
        float s = expf(hv[tid] - m) + expf(hv[tid + 32] - m);
        #pragma unroll
        for (int o = 16; o; o >>= 1) s += __shfl_xor_sync(0xffffffffu, s, o);
        if (tid == 0) red[0] = m + logf(s);
    }
    __syncthreads();
    if (tid < EMBED) emb[tid] = hv[tid] - red[0];
    __syncthreads();

    // Stage B: fc1 finish — 4 threads/row, coalesced.
    {
        int r = tid >> 2, q = tid & 3;
        const float4* __restrict__ w4 = (const float4*)fc1_w;
        const float4* __restrict__ e4 = (const float4*)emb;
        float acc = 0.0f;
        #pragma unroll
        for (int i = 0; i < 4; i++) {
            float4 w = w4[(size_t)r * ROW_F4 + (N_NODES / 4) + q * 4 + i];
            float4 e = e4[q * 4 + i];
            acc += w.x * e.x + w.y * e.y + w.z * e.z + w.w * e.w;
        }
        acc += __shfl_down_sync(0xffffffffu, acc, 2, 4);
        acc += __shfl_down_sync(0xffffffffu, acc, 1, 4);
        if (q == 0) y1s[r] = fmaxf(acc + g_fc1p[r] + fc1_b[r], 0.0f);
    }
    __syncthreads();

    // Stage C: fc2 — 4 threads/output.
    {
        int o = tid >> 2, q = tid & 3;
        const float4* __restrict__ w4 = (const float4*)(fc2_w + (size_t)o * HID0);
        const float4* __restrict__ y4 = (const float4*)y1s;
        float acc = 0.0f;
        #pragma unroll
        for (int i = 0; i < 16; i++) {
            float4 w = w4[i * 4 + q];
            float4 y = y4[i * 4 + q];
            acc += w.x * y.x + w.y * y.y + w.z * y.z + w.w * y.w;
        }
        acc += __shfl_down_sync(0xffffffffu, acc, 2, 4);
        acc += __shfl_down_sync(0xffffffffu, acc, 1, 4);
        if (q == 0) y2s[o] = fmaxf(acc + fc2_b[o], 0.0f);
    }
    __syncthreads();

    // Stage D: fc3 — 8 threads/output.
    {
        int o = tid >> 3, q = tid & 7;
        const float4* __restrict__ w4 = (const float4*)(fc3_w + (size_t)o * HID1);
        const float4* __restrict__ y4 = (const float4*)y2s;
        float acc = 0.0f;
        #pragma unroll
        for (int i = 0; i < 8; i++) {
            float4 w = w4[i * 8 + q];
            float4 y = y4[i * 8 + q];
            acc += w.x * y.x + w.y * y.y + w.z * y.z + w.w * y.w;
        }
        acc += __shfl_down_sync(0xffffffffu, acc, 4, 8);
        acc += __shfl_down_sync(0xffffffffu, acc, 2, 8);
        acc += __shfl_down_sync(0xffffffffu, acc, 1, 8);
        if (q == 0 && o < HID2) g_y3[o] = fmaxf(acc + fc3_b[o], 0.0f);
    }
}

// K5: fc4 — warp per output; preload weights into regs BEFORE gridsync
// (overlaps k_tail), then consume y3.
__global__ void __launch_bounds__(256) k_fc4(const float* __restrict__ fc4_w,
                                             const float* __restrict__ fc4_b,
                                             float* __restrict__ out) {
    int tid = threadIdx.x;
    int warp = tid >> 5, lane = tid & 31;
    int a = blockIdx.x * 8 + warp;
    // Preload (independent of tail):
    float4 w = ((const float4*)(fc4_w + (size_t)a * HID2))[lane];
    float b = fc4_b[a];

    PDL_WAIT();   // need g_y3

    float4 y = ((const float4*)g_y3)[lane];
    float acc = w.x * y.x + w.y * y.y + w.z * y.z + w.w * y.w;
    #pragma unroll
    for (int o = 16; o; o >>= 1) acc += __shfl_down_sync(0xffffffffu, acc, o);
    if (lane == 0) out[a] = fmaxf(acc + b, 0.0f);
}

// ---- host launch helpers ----
template <typename... Args>
static inline void launch_pdl(void (*kern)(Args...), dim3 grid, dim3 block,
                              Args... args) {
    cudaLaunchConfig_t cfg = {};
    cfg.gridDim = grid;
    cfg.blockDim = block;
    cfg.dynamicSmemBytes = 0;
    cfg.stream = 0;
    cudaLaunchAttribute attr[1];
    attr[0].id = cudaLaunchAttributeProgrammaticStreamSerialization;
    attr[0].val.programmaticStreamSerializationAllowed = 1;
    cfg.attrs = attr;
    cfg.numAttrs = 1;
    cudaLaunchKernelEx(&cfg, kern, args...);
}

extern "C" void kernel_launch(void* const* d_in, const int* in_sizes, int n_in,
                              void* d_out, int out_size) {
    const float* state = (const float*)d_in[0];
    const int*   start = (const int*)d_in[1];
    const float* gc1_w = (const float*)d_in[2];
    const float* gc1_b = (const float*)d_in[3];
    const float* gc2_w = (const float*)d_in[4];
    const float* gc2_b = (const float*)d_in[5];
    const float* fc1_w = (const float*)d_in[6];
    const float* fc1_b = (const float*)d_in[7];
    const float* fc2_w = (const float*)d_in[8];
    const float* fc2_b = (const float*)d_in[9];
    const float* fc3_w = (const float*)d_in[10];
    const float* fc3_b = (const float*)d_in[11];
    const float* fc4_w = (const float*)d_in[12];
    const float* fc4_b = (const float*)d_in[13];
    float* out = (float*)d_out;

    k_diag<<<N_NODES / 256, 256>>>(state);
    launch_pdl(k_matvec_fc1p, dim3(N_NODES / RPB + HID0), dim3(256),
               state, start, fc1_w);
    launch_pdl(k_t_pf, dim3(128), dim3(256),
               state, start, gc1_w, gc1_b, gc2_w, fc1_w, fc2_w, fc3_w, fc4_w);
    launch_pdl(k_tail, dim3(1), dim3(1024),
               gc2_w, gc2_b, fc1_w, fc1_b, fc2_w, fc2_b, fc3_w, fc3_b);
    launch_pdl(k_fc4, dim3(ACTION / 8), dim3(256), fc4_w, fc4_b, out);
}

// round 7
// speedup vs baseline: 1.2646x; 1.0412x over previous
#include <cuda_runtime.h>
#include <cuda_bf16.h>
#include <math.h>

#define N_NODES 8192
#define EMBED   64
#define HID0    256
#define HID1    256
#define HID2    128
#define ACTION  8192
#define IN_SIZE (N_NODES + EMBED)   // 8256
#define ROW_F4  (IN_SIZE / 4)       // 2064
#define RPB 8

#if defined(__CUDA_ARCH__) && (__CUDA_ARCH__ >= 900)
#define PDL_TRIGGER()  cudaTriggerProgrammaticLaunchCompletion()
#define PDL_WAIT()     cudaGridDependencySynchronize()
#else
#define PDL_TRIGGER()
#define PDL_WAIT()
#endif

// ---- scratch ----
__device__ float g_x[N_NODES];
__device__ float g_s[N_NODES];
__device__ float g_t[HID0];
__device__ float g_fc1p[HID0];
__device__ float g_y1[HID0];
__device__ float g_y2[HID1];
__device__ float g_y3[HID2];

// K1: extract diagonal
__global__ void k_diag(const float* __restrict__ state) {
    PDL_TRIGGER();
    int i = blockIdx.x * blockDim.x + threadIdx.x;
    if (i < N_NODES) g_x[i] = state[(size_t)i * (N_NODES + 1)];
}

// K2: blocks [0,1024): s = state@x - x^2 (waits on diag)
//     blocks [1024,1280): fc1 partials (independent -> overlap diag)
__global__ void __launch_bounds__(256) k_matvec_fc1p(const float* __restrict__ state,
                                                     const int* __restrict__ start_p,
                                                     const float* __restrict__ fc1_w) {
    PDL_TRIGGER();
    if (blockIdx.x < N_NODES / RPB) {
        PDL_WAIT();   // need g_x
        int r0 = blockIdx.x * RPB;
        const float4* __restrict__ base = (const float4*)(state + (size_t)r0 * N_NODES);
        const float4* __restrict__ xp = (const float4*)g_x;
        float acc[RPB];
        #pragma unroll
        for (int r = 0; r < RPB; r++) acc[r] = 0.0f;
        for (int j = threadIdx.x; j < N_NODES / 4; j += 256) {
            float4 xv = xp[j];
            #pragma unroll
            for (int r = 0; r < RPB; r++) {
                float4 a = base[(size_t)r * (N_NODES / 4) + j];
                acc[r] += a.x * xv.x + a.y * xv.y + a.z * xv.z + a.w * xv.w;
            }
        }
        int lane = threadIdx.x & 31, wid = threadIdx.x >> 5;
        #pragma unroll
        for (int r = 0; r < RPB; r++)
            #pragma unroll
            for (int o = 16; o; o >>= 1) acc[r] += __shfl_down_sync(0xffffffffu, acc[r], o);
        __shared__ float sh[RPB][8];
        if (lane == 0) {
            #pragma unroll
            for (int r = 0; r < RPB; r++) sh[r][wid] = acc[r];
        }
        __syncthreads();
        if (threadIdx.x < RPB * 8) {
            int r = threadIdx.x >> 3, w = threadIdx.x & 7;
            float v = sh[r][w];
            v += __shfl_down_sync(0xffffffffu, v, 4, 8);
            v += __shfl_down_sync(0xffffffffu, v, 2, 8);
            v += __shfl_down_sync(0xffffffffu, v, 1, 8);
            if (w == 0) {
                int row = r0 + r;
                float xi = g_x[row];
                g_s[row] = v - xi * xi;
            }
        }
    } else {
        int r = blockIdx.x - N_NODES / RPB;
        int st = *start_p;
        const float4* __restrict__ w4 = (const float4*)(fc1_w + (size_t)r * IN_SIZE);
        const float4* __restrict__ s4 = (const float4*)(state + (size_t)st * N_NODES);
        float acc = 0.0f;
        #pragma unroll 8
        for (int j = threadIdx.x; j < N_NODES / 4; j += 256) {
            float4 a = w4[j];
            float4 b = s4[j];
            acc += a.x * b.x + a.y * b.y + a.z * b.z + a.w * b.w;
        }
        int lane = threadIdx.x & 31, wid = threadIdx.x >> 5;
        #pragma unroll
        for (int o = 16; o; o >>= 1) acc += __shfl_down_sync(0xffffffffu, acc, o);
        __shared__ float sh2[8];
        if (lane == 0) sh2[wid] = acc;
        __syncthreads();
        if (threadIdx.x < 8) {
            float v = sh2[threadIdx.x];
            v += __shfl_down_sync(0xffu, v, 4, 8);
            v += __shfl_down_sync(0xffu, v, 2, 8);
            v += __shfl_down_sync(0xffu, v, 1, 8);
            if (threadIdx.x == 0) g_fc1p[r] = v;
        }
    }
}

// K3: k_t, 64 blocks, 4 outputs each (waits on matvec).
__global__ void __launch_bounds__(256) k_t(const float* __restrict__ state,
                                           const int* __restrict__ start_p,
                                           const float* __restrict__ gc1_w,
                                           const float* __restrict__ gc1_b) {
    PDL_TRIGGER();
    int j0 = blockIdx.x * 4;
    float w0 = gc1_w[j0], w1 = gc1_w[j0 + 1], w2 = gc1_w[j0 + 2], w3 = gc1_w[j0 + 3];
    float b0 = gc1_b[j0], b1 = gc1_b[j0 + 1], b2 = gc1_b[j0 + 2], b3 = gc1_b[j0 + 3];
    int st = *start_p;
    const float* __restrict__ row = state + (size_t)st * N_NODES;
    PDL_WAIT();   // need g_s
    float a0 = 0.f, a1 = 0.f, a2 = 0.f, a3 = 0.f;
    for (int i = threadIdx.x; i < N_NODES; i += 256) {
        float a = (i == st) ? 0.0f : row[i];
        float s = g_s[i];
        a0 += a * fmaxf(fmaf(s, w0, b0), 0.0f);
        a1 += a * fmaxf(fmaf(s, w1, b1), 0.0f);
        a2 += a * fmaxf(fmaf(s, w2, b2), 0.0f);
        a3 += a * fmaxf(fmaf(s, w3, b3), 0.0f);
    }
    float acc[4] = {a0, a1, a2, a3};
    int lane = threadIdx.x & 31, wid = threadIdx.x >> 5;
    #pragma unroll
    for (int r = 0; r < 4; r++)
        #pragma unroll
        for (int o = 16; o; o >>= 1) acc[r] += __shfl_down_sync(0xffffffffu, acc[r], o);
    __shared__ float sh[4][8];
    if (lane == 0) {
        #pragma unroll
        for (int r = 0; r < 4; r++) sh[r][wid] = acc[r];
    }
    __syncthreads();
    if (threadIdx.x < 32) {
        int r = threadIdx.x >> 3, w = threadIdx.x & 7;
        float v = sh[r][w];
        v += __shfl_down_sync(0xffffffffu, v, 4, 8);
        v += __shfl_down_sync(0xffffffffu, v, 2, 8);
        v += __shfl_down_sync(0xffffffffu, v, 1, 8);
        if (w == 0) g_t[j0 + r] = v;
    }
}

// K4 (1 block, 1024 threads, dynamic smem): preload gc2_w + fc1 tail + biases
// into smem BEFORE the dependency gate; then emb -> softmax -> fc1 finish.
__global__ void __launch_bounds__(1024) k_emb_fc1(const float* __restrict__ gc2_w,
                                                  const float* __restrict__ gc2_b,
                                                  const float* __restrict__ fc1_w,
                                                  const float* __restrict__ fc1_b) {
    PDL_TRIGGER();
    extern __shared__ float dyn[];
    float* sm_gc2  = dyn;                       // 16384 floats (gc2_w, [j][c])
    float* sm_fc1t = dyn + HID0 * EMBED;        // 16384 floats ([r][64])
    float* sm_fc1b = sm_fc1t + HID0 * EMBED;    // 256
    float* sm_gc2b = sm_fc1b + HID0;            // 64

    __shared__ float ts[HID0];
    __shared__ float part[16][EMBED];
    __shared__ float hv[EMBED];
    __shared__ float emb[EMBED];
    __shared__ float red[1];
    int tid = threadIdx.x;

    // ---- pre-gate weight staging (overlaps k_t) ----
    {
        const float4* __restrict__ src = (const float4*)gc2_w;
        float4* dst = (float4*)sm_gc2;
        for (int i = tid; i < HID0 * EMBED / 4; i += 1024) dst[i] = src[i];
        const float4* __restrict__ w4 = (const float4*)fc1_w;
        float4* dst2 = (float4*)sm_fc1t;
        for (int i = tid; i < HID0 * 16; i += 1024) {
            int r = i >> 4, c = i & 15;
            dst2[i] = w4[(size_t)r * ROW_F4 + (N_NODES / 4) + c];
        }
        if (tid < HID0) sm_fc1b[tid] = fc1_b[tid];
        if (tid < EMBED) sm_gc2b[tid] = gc2_b[tid];
    }
    __syncthreads();

    PDL_WAIT();   // need g_t, g_fc1p

    if (tid < HID0) ts[tid] = g_t[tid];
    __syncthreads();

    // Stage A: u[c] = sum_j ts[j] * gc2[j,c], 16 partials
    {
        int c = tid & 63, p = tid >> 6;
        float u = 0.0f;
        #pragma unroll
        for (int j = p * 16; j < p * 16 + 16; j++)
            u = fmaf(ts[j], sm_gc2[j * EMBED + c], u);
        part[p][c] = u;
    }
    __syncthreads();
    if (tid < EMBED) {
        float h = 0.0f;
        #pragma unroll
        for (int q = 0; q < 16; q++) h += part[q][tid];
        hv[tid] = fmaxf(h + sm_gc2b[tid], 0.0f);
    }
    __syncthreads();
    if (tid < 32) {
        float m = fmaxf(hv[tid], hv[tid + 32]);
        #pragma unroll
        for (int o = 16; o; o >>= 1) m = fmaxf(m, __shfl_xor_sync(0xffffffffu, m, o));
        float s = expf(hv[tid] - m) + expf(hv[tid + 32] - m);
        #pragma unroll
        for (int o = 16; o; o >>= 1) s += __shfl_xor_sync(0xffffffffu, s, o);
        if (tid == 0) red[0] = m + logf(s);
    }
    __syncthreads();
    if (tid < EMBED) emb[tid] = hv[tid] - red[0];
    __syncthreads();

    // Stage B: fc1 finish from smem — 4 threads per row.
    {
        int r = tid >> 2, q = tid & 3;
        const float4* __restrict__ w4 = (const float4*)(sm_fc1t + r * EMBED);
        const float4* __restrict__ e4 = (const float4*)emb;
        float acc = 0.0f;
        #pragma unroll
        for (int i = 0; i < 4; i++) {
            float4 w = w4[q * 4 + i];
            float4 e = e4[q * 4 + i];
            acc += w.x * e.x + w.y * e.y + w.z * e.z + w.w * e.w;
        }
        acc += __shfl_down_sync(0xffffffffu, acc, 2, 4);
        acc += __shfl_down_sync(0xffffffffu, acc, 1, 4);
        if (q == 0) g_y1[r] = fmaxf(acc + g_fc1p[r] + sm_fc1b[r], 0.0f);
    }
}

// K5: fc2 — warp per output; weights preloaded to regs pre-gate.
__global__ void __launch_bounds__(256) k_fc2(const float* __restrict__ fc2_w,
                                             const float* __restrict__ fc2_b) {
    PDL_TRIGGER();
    int tid = threadIdx.x, warp = tid >> 5, lane = tid & 31;
    int o = blockIdx.x * 8 + warp;
    const float4* __restrict__ w4 = (const float4*)(fc2_w + (size_t)o * HID0);
    float4 wa = w4[lane], wb = w4[lane + 32];
    float b = fc2_b[o];
    PDL_WAIT();   // need g_y1
    const float4* __restrict__ y4 = (const float4*)g_y1;
    float4 ya = y4[lane], yb = y4[lane + 32];
    float acc = wa.x * ya.x + wa.y * ya.y + wa.z * ya.z + wa.w * ya.w +
                wb.x * yb.x + wb.y * yb.y + wb.z * yb.z + wb.w * yb.w;
    #pragma unroll
    for (int off = 16; off; off >>= 1) acc += __shfl_down_sync(0xffffffffu, acc, off);
    if (lane == 0) g_y2[o] = fmaxf(acc + b, 0.0f);
}

// K6: fc3 — warp per output; weights preloaded pre-gate.
__global__ void __launch_bounds__(256) k_fc3(const float* __restrict__ fc3_w,
                                             const float* __restrict__ fc3_b) {
    PDL_TRIGGER();
    int tid = threadIdx.x, warp = tid >> 5, lane = tid & 31;
    int o = blockIdx.x * 8 + warp;
    const float4* __restrict__ w4 = (const float4*)(fc3_w + (size_t)o * HID1);
    float4 wa = w4[lane], wb = w4[lane + 32];
    float b = fc3_b[o];
    PDL_WAIT();   // need g_y2
    const float4* __restrict__ y4 = (const float4*)g_y2;
    float4 ya = y4[lane], yb = y4[lane + 32];
    float acc = wa.x * ya.x + wa.y * ya.y + wa.z * ya.z + wa.w * ya.w +
                wb.x * yb.x + wb.y * yb.y + wb.z * yb.z + wb.w * yb.w;
    #pragma unroll
    for (int off = 16; off; off >>= 1) acc += __shfl_down_sync(0xffffffffu, acc, off);
    if (lane == 0) g_y3[o] = fmaxf(acc + b, 0.0f);
}

// K7: fc4 — warp per output; weights preloaded pre-gate.
__global__ void __launch_bounds__(256) k_fc4(const float* __restrict__ fc4_w,
                                             const float* __restrict__ fc4_b,
                                             float* __restrict__ out) {
    int tid = threadIdx.x, warp = tid >> 5, lane = tid & 31;
    int a = blockIdx.x * 8 + warp;
    float4 w = ((const float4*)(fc4_w + (size_t)a * HID2))[lane];
    float b = fc4_b[a];
    PDL_WAIT();   // need g_y3
    float4 y = ((const float4*)g_y3)[lane];
    float acc = w.x * y.x + w.y * y.y + w.z * y.z + w.w * y.w;
    #pragma unroll
    for (int o = 16; o; o >>= 1) acc += __shfl_down_sync(0xffffffffu, acc, o);
    if (lane == 0) out[a] = fmaxf(acc + b, 0.0f);
}

// ---- host launch helper ----
template <typename... Args>
static inline void launch_pdl(void (*kern)(Args...), dim3 grid, dim3 block,
                              unsigned smem, Args... args) {
    cudaLaunchConfig_t cfg = {};
    cfg.gridDim = grid;
    cfg.blockDim = block;
    cfg.dynamicSmemBytes = smem;
    cfg.stream = 0;
    cudaLaunchAttribute attr[1];
    attr[0].id = cudaLaunchAttributeProgrammaticStreamSerialization;
    attr[0].val.programmaticStreamSerializationAllowed = 1;
    cfg.attrs = attr;
    cfg.numAttrs = 1;
    cudaLaunchKernelEx(&cfg, kern, args...);
}

extern "C" void kernel_launch(void* const* d_in, const int* in_sizes, int n_in,
                              void* d_out, int out_size) {
    const float* state = (const float*)d_in[0];
    const int*   start = (const int*)d_in[1];
    const float* gc1_w = (const float*)d_in[2];
    const float* gc1_b = (const float*)d_in[3];
    const float* gc2_w = (const float*)d_in[4];
    const float* gc2_b = (const float*)d_in[5];
    const float* fc1_w = (const float*)d_in[6];
    const float* fc1_b = (const float*)d_in[7];
    const float* fc2_w = (const float*)d_in[8];
    const float* fc2_b = (const float*)d_in[9];
    const float* fc3_w = (const float*)d_in[10];
    const float* fc3_b = (const float*)d_in[11];
    const float* fc4_w = (const float*)d_in[12];
    const float* fc4_b = (const float*)d_in[13];
    float* out = (float*)d_out;

    const unsigned EMB_SMEM = (HID0 * EMBED * 2 + HID0 + EMBED) * sizeof(float);
    static bool attr_set = false;
    if (!attr_set) {
        cudaFuncSetAttribute(k_emb_fc1, cudaFuncAttributeMaxDynamicSharedMemorySize,
                             EMB_SMEM);
        attr_set = true;
    }

    k_diag<<<N_NODES / 256, 256>>>(state);
    launch_pdl(k_matvec_fc1p, dim3(N_NODES / RPB + HID0), dim3(256), 0u,
               state, start, fc1_w);
    launch_pdl(k_t, dim3(64), dim3(256), 0u, state, start, gc1_w, gc1_b);
    launch_pdl(k_emb_fc1, dim3(1), dim3(1024), EMB_SMEM,
               gc2_w, gc2_b, fc1_w, fc1_b);
    launch_pdl(k_fc2, dim3(HID1 / 8), dim3(256), 0u, fc2_w, fc2_b);
    launch_pdl(k_fc3, dim3(HID2 / 8), dim3(256), 0u, fc3_w, fc3_b);
    launch_pdl(k_fc4, dim3(ACTION / 8), dim3(256), 0u, fc4_w, fc4_b, out);
}

// round 8
// speedup vs baseline: 1.4281x; 1.1293x over previous
#include <cuda_runtime.h>
#include <cuda_bf16.h>
#include <math.h>

#define N_NODES 8192
#define EMBED   64
#define HID0    256
#define HID1    256
#define HID2    128
#define ACTION  8192
#define IN_SIZE (N_NODES + EMBED)   // 8256
#define ROW_F4  (IN_SIZE / 4)       // 2064
#define RPB 8
#define TREP 4                       // g_t replicas to spread atomic contention

#if defined(__CUDA_ARCH__) && (__CUDA_ARCH__ >= 900)
#define PDL_TRIGGER()  cudaTriggerProgrammaticLaunchCompletion()
#define PDL_WAIT()     cudaGridDependencySynchronize()
#else
#define PDL_TRIGGER()
#define PDL_WAIT()
#endif

// ---- scratch ----
__device__ float g_x[N_NODES];
__device__ float g_t_rep[TREP][HID0];
__device__ float g_fc1p[HID0];
__device__ float g_y1[HID0];
__device__ float g_y2[HID1];
__device__ float g_y3[HID2];

// K1: extract diagonal + zero t replicas
__global__ void k_diag(const float* __restrict__ state) {
    PDL_TRIGGER();
    int i = blockIdx.x * blockDim.x + threadIdx.x;
    if (i < TREP * HID0) ((float*)g_t_rep)[i] = 0.0f;
    if (i < N_NODES) g_x[i] = state[(size_t)i * (N_NODES + 1)];
}

// K2: blocks [0,1024): s for 8 rows (in-register) + their contribution to t
//     blocks [1024,1280): fc1 partials (independent -> overlap diag)
__global__ void __launch_bounds__(256) k_matvec_fc1p(const float* __restrict__ state,
                                                     const int* __restrict__ start_p,
                                                     const float* __restrict__ gc1_w,
                                                     const float* __restrict__ gc1_b,
                                                     const float* __restrict__ fc1_w) {
    PDL_TRIGGER();
    int tid = threadIdx.x;
    if (blockIdx.x < N_NODES / RPB) {
        // pre-gate loads (inputs only)
        float wj = gc1_w[tid];
        float bj = gc1_b[tid];
        int st = *start_p;

        PDL_WAIT();   // need g_x + zeroed g_t_rep

        int r0 = blockIdx.x * RPB;
        const float4* __restrict__ base = (const float4*)(state + (size_t)r0 * N_NODES);
        const float4* __restrict__ xp = (const float4*)g_x;
        float acc[RPB];
        #pragma unroll
        for (int r = 0; r < RPB; r++) acc[r] = 0.0f;
        for (int j = tid; j < N_NODES / 4; j += 256) {
            float4 xv = xp[j];
            #pragma unroll
            for (int r = 0; r < RPB; r++) {
                float4 a = base[(size_t)r * (N_NODES / 4) + j];
                acc[r] += a.x * xv.x + a.y * xv.y + a.z * xv.z + a.w * xv.w;
            }
        }
        int lane = tid & 31, wid = tid >> 5;
        #pragma unroll
        for (int r = 0; r < RPB; r++)
            #pragma unroll
            for (int o = 16; o; o >>= 1) acc[r] += __shfl_down_sync(0xffffffffu, acc[r], o);
        __shared__ float sh[RPB][8];
        __shared__ float s_sh[RPB];
        __shared__ float a_sh[RPB];
        if (lane == 0) {
            #pragma unroll
            for (int r = 0; r < RPB; r++) sh[r][wid] = acc[r];
        }
        __syncthreads();
        if (tid < RPB * 8) {
            int r = tid >> 3, w = tid & 7;
            float v = sh[r][w];
            v += __shfl_down_sync(0xffffffffu, v, 4, 8);
            v += __shfl_down_sync(0xffffffffu, v, 2, 8);
            v += __shfl_down_sync(0xffffffffu, v, 1, 8);
            if (w == 0) {
                int row = r0 + r;
                float xi = g_x[row];
                s_sh[r] = v - xi * xi;
                a_sh[r] = (row == st) ? 0.0f : state[(size_t)st * N_NODES + row];
            }
        }
        __syncthreads();
        // This block's 8 rows' contribution to t[tid]:
        float c = 0.0f;
        #pragma unroll
        for (int r = 0; r < RPB; r++)
            c += a_sh[r] * fmaxf(fmaf(s_sh[r], wj, bj), 0.0f);
        atomicAdd(&g_t_rep[blockIdx.x & (TREP - 1)][tid], c);
    } else {
        // fc1 partial: one block per output row r (independent of diag)
        int r = blockIdx.x - N_NODES / RPB;
        int st = *start_p;
        const float4* __restrict__ w4 = (const float4*)(fc1_w + (size_t)r * IN_SIZE);
        const float4* __restrict__ s4 = (const float4*)(state + (size_t)st * N_NODES);
        float acc = 0.0f;
        #pragma unroll 8
        for (int j = tid; j < N_NODES / 4; j += 256) {
            float4 a = w4[j];
            float4 b = s4[j];
            acc += a.x * b.x + a.y * b.y + a.z * b.z + a.w * b.w;
        }
        int lane = tid & 31, wid = tid >> 5;
        #pragma unroll
        for (int o = 16; o; o >>= 1) acc += __shfl_down_sync(0xffffffffu, acc, o);
        __shared__ float sh2[8];
        if (lane == 0) sh2[wid] = acc;
        __syncthreads();
        if (tid < 8) {
            float v = sh2[tid];
            v += __shfl_down_sync(0xffu, v, 4, 8);
            v += __shfl_down_sync(0xffu, v, 2, 8);
            v += __shfl_down_sync(0xffu, v, 1, 8);
            if (tid == 0) g_fc1p[r] = v;
        }
    }
}

// K3 (1 block, 1024 threads, dynamic smem): preload gc2_w + fc1 tail + biases
// pre-gate; then emb -> softmax -> fc1 finish. Gates directly on matvec.
__global__ void __launch_bounds__(1024) k_emb_fc1(const float* __restrict__ gc2_w,
                                                  const float* __restrict__ gc2_b,
                                                  const float* __restrict__ fc1_w,
                                                  const float* __restrict__ fc1_b) {
    PDL_TRIGGER();
    extern __shared__ float dyn[];
    float* sm_gc2  = dyn;                       // 16384 floats (gc2_w, [j][c])
    float* sm_fc1t = dyn + HID0 * EMBED;        // 16384 floats ([r][64])
    float* sm_fc1b = sm_fc1t + HID0 * EMBED;    // 256
    float* sm_gc2b = sm_fc1b + HID0;            // 64

    __shared__ float ts[HID0];
    __shared__ float part[16][EMBED];
    __shared__ float hv[EMBED];
    __shared__ float emb[EMBED];
    __shared__ float red[1];
    int tid = threadIdx.x;

    // ---- pre-gate weight staging (overlaps matvec) ----
    {
        const float4* __restrict__ src = (const float4*)gc2_w;
        float4* dst = (float4*)sm_gc2;
        for (int i = tid; i < HID0 * EMBED / 4; i += 1024) dst[i] = src[i];
        const float4* __restrict__ w4 = (const float4*)fc1_w;
        float4* dst2 = (float4*)sm_fc1t;
        for (int i = tid; i < HID0 * 16; i += 1024) {
            int r = i >> 4, c = i & 15;
            dst2[i] = w4[(size_t)r * ROW_F4 + (N_NODES / 4) + c];
        }
        if (tid < HID0) sm_fc1b[tid] = fc1_b[tid];
        if (tid < EMBED) sm_gc2b[tid] = gc2_b[tid];
    }
    __syncthreads();

    PDL_WAIT();   // need g_t_rep, g_fc1p (matvec grid complete)

    if (tid < HID0)
        ts[tid] = g_t_rep[0][tid] + g_t_rep[1][tid] + g_t_rep[2][tid] + g_t_rep[3][tid];
    __syncthreads();

    // Stage A: u[c] = sum_j ts[j] * gc2[j,c], 16 partials
    {
        int c = tid & 63, p = tid >> 6;
        float u = 0.0f;
        #pragma unroll
        for (int j = p * 16; j < p * 16 + 16; j++)
            u = fmaf(ts[j], sm_gc2[j * EMBED + c], u);
        part[p][c] = u;
    }
    __syncthreads();
    if (tid < EMBED) {
        float h = 0.0f;
        #pragma unroll
        for (int q = 0; q < 16; q++) h += part[q][tid];
        hv[tid] = fmaxf(h + sm_gc2b[tid], 0.0f);
    }
    __syncthreads();
    if (tid < 32) {
        float m = fmaxf(hv[tid], hv[tid + 32]);
        #pragma unroll
        for (int o = 16; o; o >>= 1) m = fmaxf(m, __shfl_xor_sync(0xffffffffu, m, o));
        float s = expf(hv[tid] - m) + expf(hv[tid + 32] - m);
        #pragma unroll
        for (int o = 16; o; o >>= 1) s += __shfl_xor_sync(0xffffffffu, s, o);
        if (tid == 0) red[0] = m + logf(s);
    }
    __syncthreads();
    if (tid < EMBED) emb[tid] = hv[tid] - red[0];
    __syncthreads();

    // fc1 finish from smem — 4 threads per row.
    {
        int r = tid >> 2, q = tid & 3;
        const float4* __restrict__ w4 = (const float4*)(sm_fc1t + r * EMBED);
        const float4* __restrict__ e4 = (const float4*)emb;
        float acc = 0.0f;
        #pragma unroll
        for (int i = 0; i < 4; i++) {
            float4 w = w4[q * 4 + i];
            float4 e = e4[q * 4 + i];
            acc += w.x * e.x + w.y * e.y + w.z * e.z + w.w * e.w;
        }
        acc += __shfl_down_sync(0xffffffffu, acc, 2, 4);
        acc += __shfl_down_sync(0xffffffffu, acc, 1, 4);
        if (q == 0) g_y1[r] = fmaxf(acc + g_fc1p[r] + sm_fc1b[r], 0.0f);
    }
}

// K4: fc2 — warp per output; weights preloaded to regs pre-gate.
__global__ void __launch_bounds__(256) k_fc2(const float* __restrict__ fc2_w,
                                             const float* __restrict__ fc2_b) {
    PDL_TRIGGER();
    int tid = threadIdx.x, warp = tid >> 5, lane = tid & 31;
    int o = blockIdx.x * 8 + warp;
    const float4* __restrict__ w4 = (const float4*)(fc2_w + (size_t)o * HID0);
    float4 wa = w4[lane], wb = w4[lane + 32];
    float b = fc2_b[o];
    PDL_WAIT();   // need g_y1
    const float4* __restrict__ y4 = (const float4*)g_y1;
    float4 ya = y4[lane], yb = y4[lane + 32];
    float acc = wa.x * ya.x + wa.y * ya.y + wa.z * ya.z + wa.w * ya.w +
                wb.x * yb.x + wb.y * yb.y + wb.z * yb.z + wb.w * yb.w;
    #pragma unroll
    for (int off = 16; off; off >>= 1) acc += __shfl_down_sync(0xffffffffu, acc, off);
    if (lane == 0) g_y2[o] = fmaxf(acc + b, 0.0f);
}

// K5: fc3 — warp per output; weights preloaded pre-gate.
__global__ void __launch_bounds__(256) k_fc3(const float* __restrict__ fc3_w,
                                             const float* __restrict__ fc3_b) {
    PDL_TRIGGER();
    int tid = threadIdx.x, warp = tid >> 5, lane = tid & 31;
    int o = blockIdx.x * 8 + warp;
    const float4* __restrict__ w4 = (const float4*)(fc3_w + (size_t)o * HID1);
    float4 wa = w4[lane], wb = w4[lane + 32];
    float b = fc3_b[o];
    PDL_WAIT();   // need g_y2
    const float4* __restrict__ y4 = (const float4*)g_y2;
    float4 ya = y4[lane], yb = y4[lane + 32];
    float acc = wa.x * ya.x + wa.y * ya.y + wa.z * ya.z + wa.w * ya.w +
                wb.x * yb.x + wb.y * yb.y + wb.z * yb.z + wb.w * yb.w;
    #pragma unroll
    for (int off = 16; off; off >>= 1) acc += __shfl_down_sync(0xffffffffu, acc, off);
    if (lane == 0) g_y3[o] = fmaxf(acc + b, 0.0f);
}

// K6: fc4 — warp per output; weights preloaded pre-gate.
__global__ void __launch_bounds__(256) k_fc4(const float* __restrict__ fc4_w,
                                             const float* __restrict__ fc4_b,
                                             float* __restrict__ out) {
    int tid = threadIdx.x, warp = tid >> 5, lane = tid & 31;
    int a = blockIdx.x * 8 + warp;
    float4 w = ((const float4*)(fc4_w + (size_t)a * HID2))[lane];
    float b = fc4_b[a];
    PDL_WAIT();   // need g_y3
    float4 y = ((const float4*)g_y3)[lane];
    float acc = w.x * y.x + w.y * y.y + w.z * y.z + w.w * y.w;
    #pragma unroll
    for (int o = 16; o; o >>= 1) acc += __shfl_down_sync(0xffffffffu, acc, o);
    if (lane == 0) out[a] = fmaxf(acc + b, 0.0f);
}

// ---- host launch helper ----
template <typename... Args>
static inline void launch_pdl(void (*kern)(Args...), dim3 grid, dim3 block,
                              unsigned smem, Args... args) {
    cudaLaunchConfig_t cfg = {};
    cfg.gridDim = grid;
    cfg.blockDim = block;
    cfg.dynamicSmemBytes = smem;
    cfg.stream = 0;
    cudaLaunchAttribute attr[1];
    attr[0].id = cudaLaunchAttributeProgrammaticStreamSerialization;
    attr[0].val.programmaticStreamSerializationAllowed = 1;
    cfg.attrs = attr;
    cfg.numAttrs = 1;
    cudaLaunchKernelEx(&cfg, kern, args...);
}

extern "C" void kernel_launch(void* const* d_in, const int* in_sizes, int n_in,
                              void* d_out, int out_size) {
    const float* state = (const float*)d_in[0];
    const int*   start = (const int*)d_in[1];
    const float* gc1_w = (const float*)d_in[2];
    const float* gc1_b = (const float*)d_in[3];
    const float* gc2_w = (const float*)d_in[4];
    const float* gc2_b = (const float*)d_in[5];
    const float* fc1_w = (const float*)d_in[6];
    const float* fc1_b = (const float*)d_in[7];
    const float* fc2_w = (const float*)d_in[8];
    const float* fc2_b = (const float*)d_in[9];
    const float* fc3_w = (const float*)d_in[10];
    const float* fc3_b = (const float*)d_in[11];
    const float* fc4_w = (const float*)d_in[12];
    const float* fc4_b = (const float*)d_in[13];
    float* out = (float*)d_out;

    const unsigned EMB_SMEM = (HID0 * EMBED * 2 + HID0 + EMBED) * sizeof(float);
    static bool attr_set = false;
    if (!attr_set) {
        cudaFuncSetAttribute(k_emb_fc1, cudaFuncAttributeMaxDynamicSharedMemorySize,
                             EMB_SMEM);
        attr_set = true;
    }

    k_diag<<<N_NODES / 256, 256>>>(state);
    launch_pdl(k_matvec_fc1p, dim3(N_NODES / RPB + HID0), dim3(256), 0u,
               state, start, gc1_w, gc1_b, fc1_w);
    launch_pdl(k_emb_fc1, dim3(1), dim3(1024), EMB_SMEM,
               gc2_w, gc2_b, fc1_w, fc1_b);
    launch_pdl(k_fc2, dim3(HID1 / 8), dim3(256), 0u, fc2_w, fc2_b);
    launch_pdl(k_fc3, dim3(HID2 / 8), dim3(256), 0u, fc3_w, fc3_b);
    launch_pdl(k_fc4, dim3(ACTION / 8), dim3(256), 0u, fc4_w, fc4_b, out);
}